// round 3
// baseline (speedup 1.0000x reference)
#include <cuda_runtime.h>
#include <cstdint>

// YOLOv1 loss, GB300 (sm_103a).
// pred/target: [16384, 7, 7, 30] fp32 (96.3 MB each). Output: scalar fp32.
// Strategy: PER-WARP double-buffered cp.async pipelines (12 independent
// load streams per SM; only __syncwarp coupling), branchless per-cell math,
// per-block reduction + one atomicAdd. HBM-streaming floor ~24us at 8TB/s.

#define N_BATCH   16384
#define N_CELLS   (N_BATCH * 49)            // 802816
#define WTILE     32                         // cells per warp-tile (1/lane)
#define THREADS   128
#define WARPS     (THREADS / 32)             // 4
#define GRID      444                        // 148 SMs * 3 blocks
#define N_WTILES  (N_CELLS / WTILE)          // 25088, exact
#define WSTRIDE   (GRID * WARPS)             // 1776 global warps

#define TILE_FLOATS_PER_TENSOR (WTILE * 30)  // 960 floats = 3840 B
#define STAGE_FLOATS (2 * TILE_FLOATS_PER_TENSOR)  // pred+targ = 1920
#define WARP_FLOATS  (2 * STAGE_FLOATS)            // double buffer = 3840
#define SMEM_BYTES   (WARPS * WARP_FLOATS * 4)     // 61440

__global__ void zero_out_kernel(float* out) { out[0] = 0.0f; }

__device__ __forceinline__ void cp_async16(void* smem_dst, const void* gmem_src) {
    uint32_t sa = (uint32_t)__cvta_generic_to_shared(smem_dst);
    asm volatile("cp.async.cg.shared.global [%0], [%1], 16;\n"
                 :: "r"(sa), "l"(gmem_src));
}
__device__ __forceinline__ void cp_commit() {
    asm volatile("cp.async.commit_group;\n" ::: "memory");
}
template <int N>
__device__ __forceinline__ void cp_wait() {
    asm volatile("cp.async.wait_group %0;\n" :: "n"(N) : "memory");
}

// Prefetch one warp-tile (pred 960 floats + targ 960 floats) into stage buf.
// 240 float4 per tensor: 7 full lane-rounds + one half-round.
__device__ __forceinline__ void prefetch_wtile(const float* __restrict__ pred,
                                               const float* __restrict__ targ,
                                               float* stage, int wtile, int lane)
{
    const float4* gp4 = (const float4*)(pred + (long)wtile * TILE_FLOATS_PER_TENSOR);
    const float4* gt4 = (const float4*)(targ + (long)wtile * TILE_FLOATS_PER_TENSOR);
    float4* sp4 = (float4*)stage;
    float4* st4 = (float4*)(stage + TILE_FLOATS_PER_TENSOR);
    #pragma unroll
    for (int k = 0; k < 7; k++) {
        int i = lane + k * 32;
        cp_async16(&sp4[i], &gp4[i]);
        cp_async16(&st4[i], &gt4[i]);
    }
    if (lane < 16) {
        int i = lane + 224;
        cp_async16(&sp4[i], &gp4[i]);
        cp_async16(&st4[i], &gt4[i]);
    }
}

// Per-cell loss (branchless; replicates reference arithmetic exactly).
__device__ __forceinline__ float cell_loss(const float* __restrict__ p,
                                           const float* __restrict__ t)
{
    float d4 = p[4] - t[4];
    float d9 = p[9] - t[9];
    float noo_l = 0.5f * (d4 * d4 + d9 * d9);

    float cls = 0.0f;
    #pragma unroll
    for (int j = 10; j < 30; j++) {
        float d = p[j] - t[j];
        cls = fmaf(d, d, cls);
    }

    float tltx = t[0] - 0.5f * t[2];
    float tlty = t[1] - 0.5f * t[3];
    float trbx = t[0] + 0.5f * t[2];
    float trby = t[1] + 0.5f * t[3];
    float area2 = (trbx - tltx) * (trby - tlty);

    float iou0 = 0.0f, iou1 = 0.0f;
    #pragma unroll
    for (int b = 0; b < 2; b++) {
        const float* q = p + b * 5;
        float pltx = q[0] - 0.5f * q[2];
        float plty = q[1] - 0.5f * q[3];
        float prbx = q[0] + 0.5f * q[2];
        float prby = q[1] + 0.5f * q[3];
        float ltx = fmaxf(pltx, tltx);
        float lty = fmaxf(plty, tlty);
        float rbx = fminf(prbx, trbx);
        float rby = fminf(prby, trby);
        // reference quirk: indicator is (rb - lt < 0)
        float inter = (((rbx - ltx) < 0.0f) ? 1.0f : 0.0f) *
                      (((rby - lty) < 0.0f) ? 1.0f : 0.0f);
        float area1 = (prbx - pltx) * (prby - plty);
        float iou = inter / (area1 + area2 - inter);
        if (b == 0) iou0 = iou; else iou1 = iou;
    }
    int idx = (iou1 > iou0) ? 1 : 0;   // argmax, tie -> box 0
    const float* rp = p + idx * 5;
    const float* rt = t + idx * 5;

    float dc = rp[4] - rt[4];
    float dx = rp[0] - rt[0];
    float dy = rp[1] - rt[1];
    float dw = sqrtf(rp[2]) - sqrtf(rt[2]);   // inputs in [0,1): sqrt safe
    float dh = sqrtf(rp[3]) - sqrtf(rt[3]);

    float obj_l = cls + dc * dc + 5.0f * (dx * dx + dy * dy + dw * dw + dh * dh);

    return (t[4] > 0.0f) ? obj_l : noo_l;
}

__global__ __launch_bounds__(THREADS)
void yolo_loss_kernel(const float* __restrict__ pred,
                      const float* __restrict__ targ,
                      float* __restrict__ out)
{
    extern __shared__ float smem[];
    const int tid  = threadIdx.x;
    const int wid  = tid >> 5;
    const int lane = tid & 31;

    float* wbuf = smem + wid * WARP_FLOATS;   // this warp's 2-stage ring

    float acc = 0.0f;
    int buf = 0;

    int wtile = blockIdx.x * WARPS + wid;     // global warp-tile id
    if (wtile < N_WTILES) {
        prefetch_wtile(pred, targ, wbuf, wtile, lane);
        cp_commit();
    }

    for (; wtile < N_WTILES; wtile += WSTRIDE) {
        int next = wtile + WSTRIDE;
        if (next < N_WTILES) {
            prefetch_wtile(pred, targ, wbuf + (buf ^ 1) * STAGE_FLOATS, next, lane);
            cp_commit();
            cp_wait<1>();          // current tile's group retired
        } else {
            cp_wait<0>();
        }
        __syncwarp();              // all lanes' copies of cur visible

        const float* stage = wbuf + buf * STAGE_FLOATS;
        acc += cell_loss(stage + lane * 30,
                         stage + TILE_FLOATS_PER_TENSOR + lane * 30);

        __syncwarp();              // reads done before this buf is refilled
        buf ^= 1;
    }

    // warp reduction, then block reduction, one atomic per block
    acc *= (1.0f / (float)N_BATCH);
    #pragma unroll
    for (int o = 16; o > 0; o >>= 1)
        acc += __shfl_down_sync(0xFFFFFFFFu, acc, o);

    __shared__ float wsum[WARPS];
    if (lane == 0) wsum[wid] = acc;
    __syncthreads();
    if (tid == 0) {
        float bs = 0.0f;
        #pragma unroll
        for (int w = 0; w < WARPS; w++) bs += wsum[w];
        atomicAdd(out, bs);
    }
}

extern "C" void kernel_launch(void* const* d_in, const int* in_sizes, int n_in,
                              void* d_out, int out_size)
{
    const float* pred = (const float*)d_in[0];
    const float* targ = (const float*)d_in[1];
    float* out = (float*)d_out;

    cudaFuncSetAttribute(yolo_loss_kernel,
                         cudaFuncAttributeMaxDynamicSharedMemorySize, SMEM_BYTES);

    zero_out_kernel<<<1, 1>>>(out);
    yolo_loss_kernel<<<GRID, THREADS, SMEM_BYTES>>>(pred, targ, out);
}